// round 3
// baseline (speedup 1.0000x reference)
#include <cuda_runtime.h>
#include <cuda_bf16.h>
#include <cstdint>

// ===========================================================================
// Warp-level bf16 MMA (m16n8k16) DAG-MLP. No sm_103a-gated instructions:
// the harness compiles via compute_103 (no 'a'), which rejects tcgen05.
// Precision: fp32 operands split into bf16 hi+lo; 3 MMA streams
// (hi*hi + hi*lo + lo*hi) with fp32 accumulation -> rel err ~1e-5.
// ===========================================================================

#define BM 64
#define BN 128
#define BK 32
#define KSTR 40                       // padded K-stride in bf16 elems (80B: conflict-free)
#define A_TB (BM * KSTR * 2)          // 5120 B
#define W_TB (BN * KSTR * 2)          // 10240 B
#define STAGE_B (2 * A_TB + 2 * W_TB) // 30720 B
#define GEMM_SMEM (2 * STAGE_B)       // 61440 B

// Scratch activations: 6 layers x [512, 2048] fp32
__device__ float g_acts[6ll * 512 * 2048];

static __device__ __forceinline__ uint32_t pack_bf2(__nv_bfloat16 a, __nv_bfloat16 b) {
    __nv_bfloat162 t; t.x = a; t.y = b;
    uint32_t u; memcpy(&u, &t, 4);
    return u;
}

static __device__ __forceinline__ void split4(const float4 v, uint2& hi, uint2& lo) {
    __nv_bfloat16 h0 = __float2bfloat16(v.x);
    __nv_bfloat16 h1 = __float2bfloat16(v.y);
    __nv_bfloat16 h2 = __float2bfloat16(v.z);
    __nv_bfloat16 h3 = __float2bfloat16(v.w);
    __nv_bfloat16 l0 = __float2bfloat16(v.x - __bfloat162float(h0));
    __nv_bfloat16 l1 = __float2bfloat16(v.y - __bfloat162float(h1));
    __nv_bfloat16 l2 = __float2bfloat16(v.z - __bfloat162float(h2));
    __nv_bfloat16 l3 = __float2bfloat16(v.w - __bfloat162float(h3));
    hi.x = pack_bf2(h0, h1); hi.y = pack_bf2(h2, h3);
    lo.x = pack_bf2(l0, l1); lo.y = pack_bf2(l2, l3);
}

static __device__ __forceinline__ void mma_bf16(
    float c[4], const uint32_t a[4], const uint32_t b[2]) {
    asm volatile(
        "mma.sync.aligned.m16n8k16.row.col.f32.bf16.bf16.f32 "
        "{%0,%1,%2,%3}, {%4,%5,%6,%7}, {%8,%9}, {%0,%1,%2,%3};"
        : "+f"(c[0]), "+f"(c[1]), "+f"(c[2]), "+f"(c[3])
        : "r"(a[0]), "r"(a[1]), "r"(a[2]), "r"(a[3]), "r"(b[0]), "r"(b[1]));
}

// ---------------------------------------------------------------------------
// Fused masked-GEMM layer:
//   out[m,n] = relu( sum_j sum_k A_j[m,k] * (W_j[n,k]*M_j[n,k]) + bscale*bias[n] )
// Tile BM=64 x BN=128, K chunks of 32, double-buffered smem, reg-staged LDG.
// ---------------------------------------------------------------------------
__global__ void __launch_bounds__(256, 1) gemm_dag_kernel(
    const float* __restrict__ A, int a_row_stride, long long a_pred_stride,
    const float* __restrict__ Wt, const float* __restrict__ Mk,
    int w_row_stride, long long w_pred_stride,
    int npred, int Kdim,
    const float* __restrict__ bias, float bscale,
    float* __restrict__ out)
{
    extern __shared__ char smem[];
    const int tid = threadIdx.x;
    const int wid = tid >> 5;
    const int lid = tid & 31;
    const int warp_m = wid >> 2;        // 0..1
    const int warp_n = wid & 3;         // 0..3
    const int gID = lid >> 2;           // 0..7
    const int tig = lid & 3;            // 0..3
    const int m_base = blockIdx.x * BM;
    const int n_base = blockIdx.y * BN;

    const int cpp   = (Kdim + BK - 1) / BK;
    const int total = npred * cpp;

    // per-thread gmem-load mapping
    // A tile: 64x32 fp32 = 512 float4, 2 per thread
    // W/M tile: 128x32 fp32 = 1024 float4, 4 per thread
    float4 ra[2];
    float4 rw[4];

    float acc[2][4][4];
    #pragma unroll
    for (int mf = 0; mf < 2; ++mf)
        #pragma unroll
        for (int nf = 0; nf < 4; ++nf)
            #pragma unroll
            for (int e = 0; e < 4; ++e) acc[mf][nf][e] = 0.f;

    auto load_chunk = [&](int g) {
        const int j  = g / cpp;
        const int k0 = (g - j * cpp) * BK;
        const float* Aj = A + (size_t)j * a_pred_stride;
        const float* Wj = Wt + (size_t)j * w_pred_stride;
        const float* Mj = Mk ? (Mk + (size_t)j * w_pred_stride) : nullptr;
        #pragma unroll
        for (int i = 0; i < 2; ++i) {
            const int idx = tid + i * 256;
            const int row = idx >> 3;
            const int col = (idx & 7) * 4;
            if (k0 + col < Kdim)
                ra[i] = *(const float4*)(Aj + (size_t)(m_base + row) * a_row_stride + k0 + col);
            else
                ra[i] = make_float4(0.f, 0.f, 0.f, 0.f);
        }
        #pragma unroll
        for (int i = 0; i < 4; ++i) {
            const int idx = tid + i * 256;
            const int row = idx >> 3;
            const int col = (idx & 7) * 4;
            if (k0 + col < Kdim) {
                const size_t off = (size_t)(n_base + row) * w_row_stride + k0 + col;
                float4 wv = *(const float4*)(Wj + off);
                if (Mj) {
                    const float4 mv = *(const float4*)(Mj + off);
                    wv.x *= mv.x; wv.y *= mv.y; wv.z *= mv.z; wv.w *= mv.w;
                }
                rw[i] = wv;
            } else {
                rw[i] = make_float4(0.f, 0.f, 0.f, 0.f);
            }
        }
    };

    auto store_chunk = [&](int stage) {
        char* sAh = smem + stage * STAGE_B;
        char* sAl = sAh + A_TB;
        char* sWh = sAl + A_TB;
        char* sWl = sWh + W_TB;
        #pragma unroll
        for (int i = 0; i < 2; ++i) {
            const int idx = tid + i * 256;
            const int row = idx >> 3;
            const int col = (idx & 7) * 4;
            uint2 hi, lo;
            split4(ra[i], hi, lo);
            const int so = (row * KSTR + col) * 2;
            *(uint2*)(sAh + so) = hi;
            *(uint2*)(sAl + so) = lo;
        }
        #pragma unroll
        for (int i = 0; i < 4; ++i) {
            const int idx = tid + i * 256;
            const int row = idx >> 3;
            const int col = (idx & 7) * 4;
            uint2 hi, lo;
            split4(rw[i], hi, lo);
            const int so = (row * KSTR + col) * 2;
            *(uint2*)(sWh + so) = hi;
            *(uint2*)(sWl + so) = lo;
        }
    };

    // prologue
    load_chunk(0);
    store_chunk(0);
    __syncthreads();

    for (int g = 0; g < total; ++g) {
        const int stage = g & 1;
        if (g + 1 < total) load_chunk(g + 1);   // LDGs in flight during compute

        const char* sAh = smem + stage * STAGE_B;
        const char* sAl = sAh + A_TB;
        const char* sWh = sAl + A_TB;
        const char* sWl = sWh + W_TB;

        #pragma unroll
        for (int ks = 0; ks < 2; ++ks) {
            const int kc = ks * 16 + 2 * tig;
            uint32_t aH[2][4], aL[2][4];
            #pragma unroll
            for (int mf = 0; mf < 2; ++mf) {
                const int r0 = warp_m * 32 + mf * 16 + gID;
                const int o00 = (r0 * KSTR + kc) * 2;
                const int o10 = ((r0 + 8) * KSTR + kc) * 2;
                aH[mf][0] = *(const uint32_t*)(sAh + o00);
                aH[mf][1] = *(const uint32_t*)(sAh + o10);
                aH[mf][2] = *(const uint32_t*)(sAh + o00 + 16);
                aH[mf][3] = *(const uint32_t*)(sAh + o10 + 16);
                aL[mf][0] = *(const uint32_t*)(sAl + o00);
                aL[mf][1] = *(const uint32_t*)(sAl + o10);
                aL[mf][2] = *(const uint32_t*)(sAl + o00 + 16);
                aL[mf][3] = *(const uint32_t*)(sAl + o10 + 16);
            }
            uint32_t bH[4][2], bL[4][2];
            #pragma unroll
            for (int nf = 0; nf < 4; ++nf) {
                const int nr = warp_n * 32 + nf * 8 + gID;
                const int o = (nr * KSTR + kc) * 2;
                bH[nf][0] = *(const uint32_t*)(sWh + o);
                bH[nf][1] = *(const uint32_t*)(sWh + o + 16);
                bL[nf][0] = *(const uint32_t*)(sWl + o);
                bL[nf][1] = *(const uint32_t*)(sWl + o + 16);
            }
            #pragma unroll
            for (int mf = 0; mf < 2; ++mf)
                #pragma unroll
                for (int nf = 0; nf < 4; ++nf) {
                    mma_bf16(acc[mf][nf], aH[mf], bH[nf]);
                    mma_bf16(acc[mf][nf], aH[mf], bL[nf]);
                    mma_bf16(acc[mf][nf], aL[mf], bH[nf]);
                }
        }

        if (g + 1 < total) store_chunk(stage ^ 1);
        __syncthreads();
    }

    // epilogue: bias + relu + store
    #pragma unroll
    for (int mf = 0; mf < 2; ++mf) {
        const int r0 = m_base + warp_m * 32 + mf * 16 + gID;
        #pragma unroll
        for (int nf = 0; nf < 4; ++nf) {
            const int c0 = n_base + warp_n * 32 + nf * 8 + 2 * tig;
            const float bv0 = bscale * bias[c0];
            const float bv1 = bscale * bias[c0 + 1];
            float2 v0, v1;
            v0.x = fmaxf(acc[mf][nf][0] + bv0, 0.f);
            v0.y = fmaxf(acc[mf][nf][1] + bv1, 0.f);
            v1.x = fmaxf(acc[mf][nf][2] + bv0, 0.f);
            v1.y = fmaxf(acc[mf][nf][3] + bv1, 0.f);
            *(float2*)(out + (size_t)r0 * 2048 + c0) = v0;
            *(float2*)(out + (size_t)(r0 + 8) * 2048 + c0) = v1;
        }
    }
}

// ---------------------------------------------------------------------------
// Output layer: out[b, c] = act5[b]·w1[c] + b1[c] + act4[b]·w2[c] + b2[c]
// ---------------------------------------------------------------------------
__global__ void __launch_bounds__(256) output_kernel(
    const float* __restrict__ a5, const float* __restrict__ a4,
    const float* __restrict__ w1, const float* __restrict__ b1,
    const float* __restrict__ w2, const float* __restrict__ b2,
    float* __restrict__ out)
{
    __shared__ float red[10][257];
    const int brow = blockIdx.x;
    const int t = threadIdx.x;
    float s[10];
    #pragma unroll
    for (int c = 0; c < 10; ++c) s[c] = 0.f;
    const float* r5 = a5 + (size_t)brow * 2048;
    const float* r4 = a4 + (size_t)brow * 2048;
    for (int n = t; n < 2048; n += 256) {
        const float x5 = r5[n], x4 = r4[n];
        #pragma unroll
        for (int c = 0; c < 10; ++c)
            s[c] += x5 * w1[c * 2048 + n] + x4 * w2[c * 2048 + n];
    }
    #pragma unroll
    for (int c = 0; c < 10; ++c) red[c][t] = s[c];
    __syncthreads();
    for (int o = 128; o > 0; o >>= 1) {
        if (t < o) {
            #pragma unroll
            for (int c = 0; c < 10; ++c) red[c][t] += red[c][t + o];
        }
        __syncthreads();
    }
    if (t < 10) out[brow * 10 + t] = red[t][0] + b1[t] + b2[t];
}

// ---------------------------------------------------------------------------
// kernel_launch
// ---------------------------------------------------------------------------
extern "C" void kernel_launch(void* const* d_in, const int* in_sizes, int n_in,
                              void* d_out, int out_size)
{
    const float* x   = (const float*)d_in[0];
    const float* win = (const float*)d_in[1];
    const float* bin = (const float*)d_in[2];
    const float* W   = (const float*)d_in[3];
    const float* Mm  = (const float*)d_in[4];
    const float* b   = (const float*)d_in[5];
    const float* w1  = (const float*)d_in[6];
    const float* b1  = (const float*)d_in[7];
    const float* w2  = (const float*)d_in[8];
    const float* b2  = (const float*)d_in[9];
    float* out = (float*)d_out;

    float* acts = nullptr;
    cudaGetSymbolAddress((void**)&acts, g_acts);

    cudaFuncSetAttribute(gemm_dag_kernel,
                         cudaFuncAttributeMaxDynamicSharedMemorySize, GEMM_SMEM);

    const dim3 grid(512 / BM, 2048 / BN);   // 8 x 16 = 128 CTAs
    const dim3 blk(256);

    // input layer: act0 = relu(x @ w_in^T + b_in), K = 784, no mask
    gemm_dag_kernel<<<grid, blk, GEMM_SMEM>>>(
        x, 784, 0LL, win, nullptr, 784, 0LL, 1, 784, bin, 1.0f, acts);

    // DAG layers 1..5: act_i = relu(sum_j act_j @ (W*M)_j^T + i*b[i-1])
    int idx = 0;
    for (int i = 1; i < 6; ++i) {
        gemm_dag_kernel<<<grid, blk, GEMM_SMEM>>>(
            acts, 2048, 512LL * 2048,
            W  + (size_t)idx * 2048 * 2048,
            Mm + (size_t)idx * 2048 * 2048,
            2048, 2048LL * 2048,
            i, 2048,
            b + (size_t)(i - 1) * 2048, (float)i,
            acts + (size_t)i * 512 * 2048);
        idx += i;
    }

    // output layer
    output_kernel<<<512, 256>>>(
        acts + 5LL * 512 * 2048, acts + 4LL * 512 * 2048,
        w1, b1, w2, b2, out);
}

// round 4
// speedup vs baseline: 3.1504x; 3.1504x over previous
#include <cuda_runtime.h>
#include <cuda_bf16.h>
#include <cstdint>

// ===========================================================================
// DAG-MLP via warp-level bf16 mma.sync (m16n8k16) — compute_103-safe.
// Precision: fp32 split into bf16 hi+lo, 3 MMA streams (hh + hl + lh).
// Round-4 structure:
//   pass 1: split W*M -> Whi/Wlo bf16 scratch (one streaming pass)
//   pass 2: per-layer GEMM, pure cp.async 4-stage pipeline + ldmatrix,
//           epilogue writes fp32 acts AND pre-split bf16 acts.
// ===========================================================================

#define BM 64
#define BN 64
#define BK 32
#define KSTR 40                        // padded K stride (bf16 elems) = 80 B
#define TILE_B (64 * KSTR * 2)         // 5120 B (64 rows x 32 bf16 padded)
#define STAGE_B (4 * TILE_B)           // Ahi|Alo|Whi|Wlo = 20480 B
#define STAGES 4
#define GEMM_SMEM (STAGES * STAGE_B)   // 81920 B

// ---------------- scratch (device globals; no allocations) ----------------
__device__ __nv_bfloat16 g_Whi[15ll * 2048 * 2048];   // split(W*M) hi
__device__ __nv_bfloat16 g_Wlo[15ll * 2048 * 2048];   // split(W*M) lo
__device__ __nv_bfloat16 g_Ahi[6ll * 512 * 2048];     // split acts hi
__device__ __nv_bfloat16 g_Alo[6ll * 512 * 2048];     // split acts lo
__device__ __nv_bfloat16 g_xhi[512 * 800];            // padded input hi
__device__ __nv_bfloat16 g_xlo[512 * 800];
__device__ __nv_bfloat16 g_winhi[2048 * 800];         // padded w_in hi
__device__ __nv_bfloat16 g_winlo[2048 * 800];
__device__ float g_acts[6ll * 512 * 2048];            // fp32 acts (output layer)

// ---------------- helpers ----------------
static __device__ __forceinline__ uint32_t smem_u32(const void* p) {
    uint32_t r;
    asm("{ .reg .u64 t; cvta.to.shared.u64 t, %1; cvt.u32.u64 %0, t; }"
        : "=r"(r) : "l"(p));
    return r;
}

static __device__ __forceinline__ uint32_t pack_bf2(__nv_bfloat16 a, __nv_bfloat16 b) {
    __nv_bfloat162 t; t.x = a; t.y = b;
    uint32_t u; memcpy(&u, &t, 4);
    return u;
}

static __device__ __forceinline__ void split1(float v, __nv_bfloat16& h, __nv_bfloat16& l) {
    h = __float2bfloat16(v);
    l = __float2bfloat16(v - __bfloat162float(h));
}

static __device__ __forceinline__ void cp16(uint32_t dst, const void* src) {
    asm volatile("cp.async.cg.shared.global [%0], [%1], 16;" :: "r"(dst), "l"(src));
}

static __device__ __forceinline__ void ldm4(uint32_t r[4], uint32_t addr) {
    asm volatile("ldmatrix.sync.aligned.m8n8.x4.shared.b16 {%0,%1,%2,%3}, [%4];"
                 : "=r"(r[0]), "=r"(r[1]), "=r"(r[2]), "=r"(r[3]) : "r"(addr));
}

static __device__ __forceinline__ void mma_bf16(
    float c[4], const uint32_t a[4], uint32_t b0, uint32_t b1) {
    asm volatile(
        "mma.sync.aligned.m16n8k16.row.col.f32.bf16.bf16.f32 "
        "{%0,%1,%2,%3}, {%4,%5,%6,%7}, {%8,%9}, {%0,%1,%2,%3};"
        : "+f"(c[0]), "+f"(c[1]), "+f"(c[2]), "+f"(c[3])
        : "r"(a[0]), "r"(a[1]), "r"(a[2]), "r"(a[3]), "r"(b0), "r"(b1));
}

// ---------------- pass 1: split kernels ----------------
__global__ void __launch_bounds__(256) split_wm_kernel(
    const float4* __restrict__ W, const float4* __restrict__ M,
    uint2* __restrict__ hi, uint2* __restrict__ lo, long long n4)
{
    long long i = (long long)blockIdx.x * 256 + threadIdx.x;
    if (i >= n4) return;
    const float4 w = W[i], m = M[i];
    float p0 = w.x * m.x, p1 = w.y * m.y, p2 = w.z * m.z, p3 = w.w * m.w;
    __nv_bfloat16 h0, h1, h2, h3, l0, l1, l2, l3;
    split1(p0, h0, l0); split1(p1, h1, l1); split1(p2, h2, l2); split1(p3, h3, l3);
    hi[i] = make_uint2(pack_bf2(h0, h1), pack_bf2(h2, h3));
    lo[i] = make_uint2(pack_bf2(l0, l1), pack_bf2(l2, l3));
}

// split + pad K 784 -> 800 (zeros in tail)
__global__ void __launch_bounds__(256) split_pad_kernel(
    const float* __restrict__ src, int rows,
    __nv_bfloat16* __restrict__ hi, __nv_bfloat16* __restrict__ lo)
{
    long long i = (long long)blockIdx.x * 256 + threadIdx.x;
    if (i >= (long long)rows * 800) return;
    const int r = (int)(i / 800), c = (int)(i - (long long)r * 800);
    float v = (c < 784) ? src[(size_t)r * 784 + c] : 0.f;
    __nv_bfloat16 h, l;
    split1(v, h, l);
    hi[i] = h; lo[i] = l;
}

// ---------------- pass 2: GEMM layer kernel ----------------
//   out[m,n] = relu( sum_j sum_k A_j[m,k]*W_j[n,k] + bscale*bias[n] )
// Tiles 64x64, BK=32, 4-stage cp.async pipeline, ldmatrix fragments.
__global__ void __launch_bounds__(256, 2) gemm_bf16_kernel(
    const __nv_bfloat16* __restrict__ Ahi, const __nv_bfloat16* __restrict__ Alo,
    int a_rs, long long a_ps,
    const __nv_bfloat16* __restrict__ Whi, const __nv_bfloat16* __restrict__ Wlo,
    int w_rs, long long w_ps,
    int npred, int Kdim,
    const float* __restrict__ bias, float bscale,
    float* __restrict__ outf,
    __nv_bfloat16* __restrict__ outh, __nv_bfloat16* __restrict__ outl)
{
    extern __shared__ char smem[];
    const uint32_t sb = smem_u32(smem);
    const int tid = threadIdx.x;
    const int wid = tid >> 5;
    const int lid = tid & 31;
    const int warp_m = wid >> 2;          // 0..1
    const int warp_n = wid & 3;           // 0..3
    const int gID = lid >> 2;             // 0..7
    const int tig = lid & 3;              // 0..3
    const int m_base = blockIdx.x * BM;
    const int n_base = blockIdx.y * BN;

    const int cpp   = Kdim >> 5;          // Kdim is a multiple of 32
    const int total = npred * cpp;

    // cp.async granule mapping: 256 granules of 16B per 64x32 tile
    const int grow = tid >> 2;            // 0..63
    const int gcol = (tid & 3) * 8;       // bf16 element col 0,8,16,24
    const uint32_t sdst = sb + grow * (KSTR * 2) + (tid & 3) * 16;

    auto issue = [&](int g, int stage) {
        const int j  = g / cpp;
        const int k0 = (g - j * cpp) << 5;
        const __nv_bfloat16* Ah = Ahi + (size_t)j * a_ps + (size_t)(m_base + grow) * a_rs + k0 + gcol;
        const __nv_bfloat16* Al = Alo + (size_t)j * a_ps + (size_t)(m_base + grow) * a_rs + k0 + gcol;
        const __nv_bfloat16* Wh = Whi + (size_t)j * w_ps + (size_t)(n_base + grow) * w_rs + k0 + gcol;
        const __nv_bfloat16* Wl = Wlo + (size_t)j * w_ps + (size_t)(n_base + grow) * w_rs + k0 + gcol;
        const uint32_t d = sdst + stage * STAGE_B;
        cp16(d,              Ah);
        cp16(d + TILE_B,     Al);
        cp16(d + 2 * TILE_B, Wh);
        cp16(d + 3 * TILE_B, Wl);
    };

    float acc[2][2][4];
    #pragma unroll
    for (int mf = 0; mf < 2; ++mf)
        #pragma unroll
        for (int nf = 0; nf < 2; ++nf)
            #pragma unroll
            for (int e = 0; e < 4; ++e) acc[mf][nf][e] = 0.f;

    // ldmatrix lane addressing
    const int lrow  = lid & 15;
    const int khalf = (lid >> 4) * 8;
    const uint32_t aoff = ((warp_m * 32 + lrow) * KSTR + khalf) * 2;
    const uint32_t boff = ((warp_n * 16 + lrow) * KSTR + khalf) * 2;

    // prologue: fill 3 stages (3 commit groups)
    #pragma unroll
    for (int g = 0; g < 3; ++g) {
        if (g < total) issue(g, g);
        asm volatile("cp.async.commit_group;");
    }

    for (int g = 0; g < total; ++g) {
        asm volatile("cp.async.wait_group 2;");
        __syncthreads();
        if (g + 3 < total) issue(g + 3, (g + 3) & 3);
        asm volatile("cp.async.commit_group;");

        const uint32_t st = sb + (g & 3) * STAGE_B;
        #pragma unroll
        for (int ks = 0; ks < 2; ++ks) {
            const uint32_t ko = ks * 32;   // 16 bf16 = 32 B
            uint32_t bh[4], bl[4];
            ldm4(bh, st + 2 * TILE_B + boff + ko);
            ldm4(bl, st + 3 * TILE_B + boff + ko);
            #pragma unroll
            for (int mf = 0; mf < 2; ++mf) {
                uint32_t ah[4], al[4];
                const uint32_t ao = st + aoff + mf * (16 * KSTR * 2) + ko;
                ldm4(ah, ao);
                ldm4(al, ao + TILE_B);
                #pragma unroll
                for (int nf = 0; nf < 2; ++nf) {
                    mma_bf16(acc[mf][nf], ah, bh[nf], bh[2 + nf]);
                    mma_bf16(acc[mf][nf], ah, bl[nf], bl[2 + nf]);
                    mma_bf16(acc[mf][nf], al, bh[nf], bh[2 + nf]);
                }
            }
        }
        __syncthreads();
    }

    // epilogue: bias + relu; write fp32 acts + pre-split bf16 acts
    #pragma unroll
    for (int mf = 0; mf < 2; ++mf) {
        const int r0 = m_base + warp_m * 32 + mf * 16 + gID;
        #pragma unroll
        for (int nf = 0; nf < 2; ++nf) {
            const int c0 = n_base + warp_n * 16 + nf * 8 + 2 * tig;
            const float bv0 = bscale * bias[c0];
            const float bv1 = bscale * bias[c0 + 1];
            const float v00 = fmaxf(acc[mf][nf][0] + bv0, 0.f);
            const float v01 = fmaxf(acc[mf][nf][1] + bv1, 0.f);
            const float v10 = fmaxf(acc[mf][nf][2] + bv0, 0.f);
            const float v11 = fmaxf(acc[mf][nf][3] + bv1, 0.f);
            const size_t o0 = (size_t)r0 * 2048 + c0;
            const size_t o1 = (size_t)(r0 + 8) * 2048 + c0;
            *(float2*)(outf + o0) = make_float2(v00, v01);
            *(float2*)(outf + o1) = make_float2(v10, v11);
            __nv_bfloat16 h0, h1, l0, l1;
            split1(v00, h0, l0); split1(v01, h1, l1);
            *(uint32_t*)(outh + o0) = pack_bf2(h0, h1);
            *(uint32_t*)(outl + o0) = pack_bf2(l0, l1);
            split1(v10, h0, l0); split1(v11, h1, l1);
            *(uint32_t*)(outh + o1) = pack_bf2(h0, h1);
            *(uint32_t*)(outl + o1) = pack_bf2(l0, l1);
        }
    }
}

// ---------------- output layer ----------------
__global__ void __launch_bounds__(256) output_kernel(
    const float* __restrict__ a5, const float* __restrict__ a4,
    const float* __restrict__ w1, const float* __restrict__ b1,
    const float* __restrict__ w2, const float* __restrict__ b2,
    float* __restrict__ out)
{
    __shared__ float red[10][257];
    const int brow = blockIdx.x;
    const int t = threadIdx.x;
    float s[10];
    #pragma unroll
    for (int c = 0; c < 10; ++c) s[c] = 0.f;
    const float* r5 = a5 + (size_t)brow * 2048;
    const float* r4 = a4 + (size_t)brow * 2048;
    for (int n = t; n < 2048; n += 256) {
        const float x5 = r5[n], x4 = r4[n];
        #pragma unroll
        for (int c = 0; c < 10; ++c)
            s[c] += x5 * w1[c * 2048 + n] + x4 * w2[c * 2048 + n];
    }
    #pragma unroll
    for (int c = 0; c < 10; ++c) red[c][t] = s[c];
    __syncthreads();
    for (int o = 128; o > 0; o >>= 1) {
        if (t < o) {
            #pragma unroll
            for (int c = 0; c < 10; ++c) red[c][t] += red[c][t + o];
        }
        __syncthreads();
    }
    if (t < 10) out[brow * 10 + t] = red[t][0] + b1[t] + b2[t];
}

// ---------------- kernel_launch ----------------
extern "C" void kernel_launch(void* const* d_in, const int* in_sizes, int n_in,
                              void* d_out, int out_size)
{
    const float* x   = (const float*)d_in[0];
    const float* win = (const float*)d_in[1];
    const float* bin = (const float*)d_in[2];
    const float* W   = (const float*)d_in[3];
    const float* Mm  = (const float*)d_in[4];
    const float* b   = (const float*)d_in[5];
    const float* w1  = (const float*)d_in[6];
    const float* b1  = (const float*)d_in[7];
    const float* w2  = (const float*)d_in[8];
    const float* b2  = (const float*)d_in[9];
    float* out = (float*)d_out;

    float *acts;
    __nv_bfloat16 *whi, *wlo, *ahi, *alo, *xhi, *xlo, *wihi, *wilo;
    cudaGetSymbolAddress((void**)&acts, g_acts);
    cudaGetSymbolAddress((void**)&whi, g_Whi);
    cudaGetSymbolAddress((void**)&wlo, g_Wlo);
    cudaGetSymbolAddress((void**)&ahi, g_Ahi);
    cudaGetSymbolAddress((void**)&alo, g_Alo);
    cudaGetSymbolAddress((void**)&xhi, g_xhi);
    cudaGetSymbolAddress((void**)&xlo, g_xlo);
    cudaGetSymbolAddress((void**)&wihi, g_winhi);
    cudaGetSymbolAddress((void**)&wilo, g_winlo);

    cudaFuncSetAttribute(gemm_bf16_kernel,
                         cudaFuncAttributeMaxDynamicSharedMemorySize, GEMM_SMEM);

    // pass 1: splits
    {
        const long long n4 = 15ll * 2048 * 2048 / 4;
        split_wm_kernel<<<(int)((n4 + 255) / 256), 256>>>(
            (const float4*)W, (const float4*)Mm, (uint2*)whi, (uint2*)wlo, n4);
        split_pad_kernel<<<(512 * 800 + 255) / 256, 256>>>(x, 512, xhi, xlo);
        split_pad_kernel<<<(2048 * 800 + 255) / 256, 256>>>(win, 2048, wihi, wilo);
    }

    const dim3 grid(512 / BM, 2048 / BN);   // 8 x 32 = 256 CTAs
    const dim3 blk(256);

    // layer 0: act0 = relu(x @ w_in^T + b_in), padded K=800
    gemm_bf16_kernel<<<grid, blk, GEMM_SMEM>>>(
        xhi, xlo, 800, 0LL, wihi, wilo, 800, 0LL, 1, 800,
        bin, 1.0f, acts, ahi, alo);

    // DAG layers 1..5
    long long idx = 0;
    for (int i = 1; i < 6; ++i) {
        gemm_bf16_kernel<<<grid, blk, GEMM_SMEM>>>(
            ahi, alo, 2048, 512LL * 2048,
            whi + idx * 2048 * 2048, wlo + idx * 2048 * 2048,
            2048, 2048LL * 2048,
            i, 2048,
            b + (size_t)(i - 1) * 2048, (float)i,
            acts + (size_t)i * 512 * 2048,
            ahi + (size_t)i * 512 * 2048,
            alo + (size_t)i * 512 * 2048);
        idx += i;
    }

    output_kernel<<<512, 256>>>(
        acts + 5LL * 512 * 2048, acts + 4LL * 512 * 2048,
        w1, b1, w2, b2, out);
}